// round 15
// baseline (speedup 1.0000x reference)
#include <cuda_runtime.h>
#include <cuda_fp16.h>
#include <math.h>
#include <stdint.h>

#define BN_EPS 1e-5f

// ---------------------------------------------------------------------------
// Global scratch
// ---------------------------------------------------------------------------
__device__ __half g_w1h[128*2304];                 // k = r*256+ci
__device__ __half g_w2h[256*1152];                 // k = r*128+ci
__device__ __half g_xt [16u*4096*256];             // x^T  [b][p][ci]
__device__ __half g_y1t[16u*4096*128];             // y1^T [b][p][ci]
__device__ __half g_y2 [16u*256*4096];             // y2   [b][c][p]
__device__ __half g_y2t[16u*4096*256];             // y2^T [b][p][c]
__device__ float  g_scp[64u*256*256];              // score partials [b*4+ks][c][d]
__device__ __half g_at [16u*256*256];              // attn

// ---------------------------------------------------------------------------
__device__ __forceinline__ uint32_t smem_u32(const void* p) {
    uint32_t a;
    asm("{ .reg .u64 t; cvta.to.shared.u64 t, %1; cvt.u32.u64 %0, t; }" : "=r"(a) : "l"(p));
    return a;
}
__device__ __forceinline__ void ldsm_x4(uint32_t addr, uint32_t r[4]) {
    asm volatile("ldmatrix.sync.aligned.m8n8.x4.shared.b16 {%0,%1,%2,%3}, [%4];"
                 : "=r"(r[0]), "=r"(r[1]), "=r"(r[2]), "=r"(r[3]) : "r"(addr));
}
__device__ __forceinline__ void mma16816(float d[4], const uint32_t a[4],
                                         uint32_t b0, uint32_t b1) {
    asm volatile(
        "mma.sync.aligned.m16n8k16.row.col.f32.f16.f16.f32 "
        "{%0,%1,%2,%3}, {%4,%5,%6,%7}, {%8,%9}, {%0,%1,%2,%3};"
        : "+f"(d[0]), "+f"(d[1]), "+f"(d[2]), "+f"(d[3])
        : "r"(a[0]), "r"(a[1]), "r"(a[2]), "r"(a[3]), "r"(b0), "r"(b1));
}
__device__ __forceinline__ uint32_t sw128(uint32_t off) {
    return off ^ ((off >> 3) & 0x70);
}
__device__ __forceinline__ void cp16(uint32_t dst, const void* src, int sz) {
    asm volatile("cp.async.cg.shared.global [%0], [%1], 16, %2;"
                 :: "r"(dst), "l"(src), "r"(sz) : "memory");
}
__device__ __forceinline__ void cp_commit() {
    asm volatile("cp.async.commit_group;" ::: "memory");
}

// ---------------------------------------------------------------------------
// fp16 GEMM on HMMA. CTA tile 128(M)x64(N), warps 4(M)x2(N), warp 32x32.
// Templated K-chunk (KCH = 64 or 128) and min-CTAs-per-SM (OCC).
// 2-stage cp.async, ONE sync per chunk.
// Stage = KCH*384 bytes: A = (KCH/64) blocks [128][64]h, B after A.
// MODE 0: conv (BN+SiLU). outh [c][p] (nullable), outt [p][c] transposed
//         (nullable). B = shifted transposed image planes, k = r*CI+ci.
// MODE 1: scores partial (x 1/16 -> fp32 partial; z = b*4+kslice)
// MODE 2: out (+ residual -> fp32)
// ---------------------------------------------------------------------------
template <int MODE, int CI, int KCH, int OCC>
__global__ __launch_bounds__(256, OCC)
void gemm_fp16(const __half* __restrict__ Ag, int lda,
               const __half* __restrict__ Bg, int K,
               const float* __restrict__ p0, const float* __restrict__ p1,
               const float* __restrict__ p2, const float* __restrict__ p3,
               const float* __restrict__ resid,
               __half* __restrict__ outh, __half* __restrict__ outt,
               float* __restrict__ outf)
{
    extern __shared__ char sm[];
    constexpr int STAGE  = KCH * 384;
    constexpr int ABYTES = KCH * 256;
    constexpr int GPR    = KCH / 8;
    constexpr int RSTEP  = 256 / GPR;
    const int t    = threadIdx.x;
    const int lane = t & 31, warp = t >> 5;
    const int wm   = (warp >> 1) * 32;
    const int wn   = (warp & 1) * 32;
    const int bm = blockIdx.y, bn = blockIdx.x;
    const int b  = (MODE == 1) ? (blockIdx.z >> 2) : blockIdx.z;
    const uint32_t sb = smem_u32(sm);

    const __half *Ab, *Bb;
    if (MODE == 0) {
        Ab = Ag; Bb = Bg + (size_t)b * 4096 * CI;
    } else if (MODE == 1) {
        const int ks = blockIdx.z & 3;
        size_t o = (size_t)b * 256 * 4096 + (size_t)ks * 1024;
        Ab = Ag + o; Bb = Bg + o;
    } else {
        Ab = Ag + (size_t)b * 256 * 256; Bb = Bg + (size_t)b * 4096 * 256;
    }
    const int ldb = (MODE == 1) ? 4096 : 256;

    float acc[2][4][4];
#pragma unroll
    for (int i = 0; i < 2; ++i)
#pragma unroll
        for (int j = 0; j < 4; ++j)
#pragma unroll
            for (int q = 0; q < 4; ++q) acc[i][j][q] = 0.f;

    // Prefetch task decomposition
    const int g   = t & (GPR - 1);
    const int m0  = t / GPR;
    const int blk = g >> 3;
    const int gin = g & 7;
    const uint32_t a_row0 = (uint32_t)((bm * 128 + m0) * lda + g * 8);
    uint32_t b_row0;
    if (MODE == 0) b_row0 = (uint32_t)((bn * 64 + m0) * CI + g * 8);
    else           b_row0 = (uint32_t)((bn * 64 + m0) * ldb + g * 8);

    // Hoisted ldsm addressing
    const int a_row = (lane & 7) + ((lane >> 3) & 1) * 8;
    const int a_chk = lane >> 4;
    const int b_row = (lane & 7) + ((lane >> 4) & 1) * 8;
    const int b_chk = (lane >> 3) & 1;
    uint32_t a_base[2], a_xor[2];
#pragma unroll
    for (int mt = 0; mt < 2; ++mt) {
        const int row = wm + mt * 16 + a_row;
        a_base[mt] = row * 128; a_xor[mt] = (row & 7) << 4;
    }
    uint32_t b_base[2], b_xor[2];
#pragma unroll
    for (int ng = 0; ng < 2; ++ng) {
        const int row = wn + ng * 16 + b_row;
        b_base[ng] = row * 128; b_xor[ng] = (row & 7) << 4;
    }

    auto prefetch = [&](int kt, int stage) {
        const uint32_t base = sb + stage * STAGE;
#pragma unroll
        for (int i = 0; i < 128 / RSTEP; ++i) {
            const int m = m0 + i * RSTEP;
            cp16(base + blk * 16384 + sw128(m * 128 + gin * 16),
                 Ab + a_row0 + (uint32_t)(i * RSTEP * lda) + kt * KCH, 16);
        }
        if (MODE == 0) {
            const int r   = (kt * KCH) / CI;
            const int ci0 = kt * KCH - r * CI;
            const int dh  = r / 3 - 1, dw = (r - (r / 3) * 3) - 1;
            const int delta = (dh * 64 + dw) * CI + ci0;
            const int hh = bn + dh;                    // tile = one image row
            const bool hok = (unsigned)hh < 64u;
#pragma unroll
            for (int i = 0; i < 64 / RSTEP; ++i) {
                const int m = m0 + i * RSTEP;
                const int ww = m + dw;
                const bool ok = hok && ((unsigned)ww < 64u);
                cp16(base + ABYTES + blk * 8192 + sw128(m * 128 + gin * 16),
                     Bb + (ok ? (b_row0 + (uint32_t)(i * RSTEP * CI) + delta) : 0u),
                     ok ? 16 : 0);
            }
        } else {
#pragma unroll
            for (int i = 0; i < 64 / RSTEP; ++i) {
                const int m = m0 + i * RSTEP;
                cp16(base + ABYTES + blk * 8192 + sw128(m * 128 + gin * 16),
                     Bb + b_row0 + (uint32_t)(i * RSTEP * ldb) + kt * KCH, 16);
            }
        }
    };

    const int nch = K / KCH;
    prefetch(0, 0);
    cp_commit();

    for (int kt = 0; kt < nch; ++kt) {
        const int stage = kt & 1;
        asm volatile("cp.async.wait_group 0;" ::: "memory");
        __syncthreads();
        if (kt + 1 < nch) {
            prefetch(kt + 1, stage ^ 1);
            cp_commit();
        }

        const uint32_t abase = sb + stage * STAGE;
        const uint32_t bbase = abase + ABYTES;
#pragma unroll
        for (int ks = 0; ks < KCH / 16; ++ks) {
            const uint32_t ablk = (uint32_t)(ks >> 2) * 16384;
            const uint32_t bblk = (uint32_t)(ks >> 2) * 8192;
            const uint32_t acol = (uint32_t)(((ks & 3) * 2 + a_chk) * 16);
            const uint32_t bcol = (uint32_t)(((ks & 3) * 2 + b_chk) * 16);
            uint32_t ah[2][4];
#pragma unroll
            for (int mt = 0; mt < 2; ++mt)
                ldsm_x4(abase + ablk + a_base[mt] + (acol ^ a_xor[mt]), ah[mt]);
#pragma unroll
            for (int ng = 0; ng < 2; ++ng) {
                uint32_t bh[4];
                ldsm_x4(bbase + bblk + b_base[ng] + (bcol ^ b_xor[ng]), bh);
#pragma unroll
                for (int mt = 0; mt < 2; ++mt) {
                    mma16816(acc[mt][2 * ng],     ah[mt], bh[0], bh[1]);
                    mma16816(acc[mt][2 * ng + 1], ah[mt], bh[2], bh[3]);
                }
            }
        }
    }

    // ----------------------- epilogue -----------------------
    const int r0 = bm * 128 + wm + (lane >> 2);
    const int c0 = bn * 64 + wn + (lane & 3) * 2;

    if (MODE == 0) {
        const int CO = gridDim.y * 128;
        // Per-mt processing keeps live register set small (helps OCC=4 fit).
        if (outt) {
            uint16_t (*tt)[130] = reinterpret_cast<uint16_t(*)[130]>(sm);
            __syncthreads();
            const int co_lb = wm + (lane >> 2);
            const int p_lb  = wn + (lane & 3) * 2;
#pragma unroll
            for (int mt = 0; mt < 2; ++mt) {
#pragma unroll
                for (int half = 0; half < 2; ++half) {
                    const int co = r0 + mt * 16 + half * 8;
                    const float scl = p0[co] * rsqrtf(p3[co] + BN_EPS);
                    const float shf = p1[co] - p2[co] * scl;
                    const int co_l = co_lb + mt * 16 + half * 8;
                    __half* dst = outh ? outh + ((size_t)(b * CO + co)) * 4096 : nullptr;
#pragma unroll
                    for (int nt = 0; nt < 4; ++nt) {
                        float y0 = acc[mt][nt][2 * half]     * scl + shf;
                        float y1 = acc[mt][nt][2 * half + 1] * scl + shf;
                        y0 = y0 / (1.f + expf(-y0));
                        y1 = y1 / (1.f + expf(-y1));
                        __half2 v2h = __floats2half2_rn(y0, y1);
                        if (dst) *reinterpret_cast<__half2*>(dst + c0 + nt * 8) = v2h;
                        const int p_l = p_lb + nt * 8;
                        uint32_t v = *reinterpret_cast<uint32_t*>(&v2h);
                        tt[p_l][co_l]     = (uint16_t)v;
                        tt[p_l + 1][co_l] = (uint16_t)(v >> 16);
                    }
                }
            }
            __syncthreads();
#pragma unroll
            for (int i = 0; i < 4; ++i) {
                const int idx = t + i * 256;
                const int row = idx >> 4, gg = idx & 15;
                uint32_t w0 = (uint32_t)tt[row][gg * 8 + 0] | ((uint32_t)tt[row][gg * 8 + 1] << 16);
                uint32_t w1 = (uint32_t)tt[row][gg * 8 + 2] | ((uint32_t)tt[row][gg * 8 + 3] << 16);
                uint32_t w2 = (uint32_t)tt[row][gg * 8 + 4] | ((uint32_t)tt[row][gg * 8 + 5] << 16);
                uint32_t w3 = (uint32_t)tt[row][gg * 8 + 6] | ((uint32_t)tt[row][gg * 8 + 7] << 16);
                __half* drow = outt + ((size_t)(b * 4096 + bn * 64 + row)) * CO + bm * 128 + gg * 8;
                *reinterpret_cast<uint4*>(drow) = make_uint4(w0, w1, w2, w3);
            }
        } else if (outh) {
#pragma unroll
            for (int mt = 0; mt < 2; ++mt) {
#pragma unroll
                for (int half = 0; half < 2; ++half) {
                    const int co = r0 + mt * 16 + half * 8;
                    const float scl = p0[co] * rsqrtf(p3[co] + BN_EPS);
                    const float shf = p1[co] - p2[co] * scl;
                    __half* dst = outh + ((size_t)(b * CO + co)) * 4096;
#pragma unroll
                    for (int nt = 0; nt < 4; ++nt) {
                        float y0 = acc[mt][nt][2 * half]     * scl + shf;
                        float y1 = acc[mt][nt][2 * half + 1] * scl + shf;
                        y0 = y0 / (1.f + expf(-y0));
                        y1 = y1 / (1.f + expf(-y1));
                        *reinterpret_cast<__half2*>(dst + c0 + nt * 8) =
                            __floats2half2_rn(y0, y1);
                    }
                }
            }
        }
    } else if (MODE == 1) {
        float* obase = outf + (size_t)blockIdx.z * 256 * 256;
#pragma unroll
        for (int mt = 0; mt < 2; ++mt) {
#pragma unroll
            for (int half = 0; half < 2; ++half) {
                float* dst = obase + (size_t)(r0 + mt * 16 + half * 8) * 256;
#pragma unroll
                for (int nt = 0; nt < 4; ++nt) {
                    *reinterpret_cast<float2*>(dst + c0 + nt * 8) =
                        make_float2(acc[mt][nt][2 * half] * 0.0625f,
                                    acc[mt][nt][2 * half + 1] * 0.0625f);
                }
            }
        }
    } else {
#pragma unroll
        for (int mt = 0; mt < 2; ++mt) {
#pragma unroll
            for (int half = 0; half < 2; ++half) {
                const int c = r0 + mt * 16 + half * 8;
                const size_t base2 = ((size_t)(b * 256 + c)) * 4096;
#pragma unroll
                for (int nt = 0; nt < 4; ++nt) {
                    float2 rx = *reinterpret_cast<const float2*>(resid + base2 + c0 + nt * 8);
                    *reinterpret_cast<float2*>(outf + base2 + c0 + nt * 8) =
                        make_float2(acc[mt][nt][2 * half] + rx.x,
                                    acc[mt][nt][2 * half + 1] + rx.y);
                }
            }
        }
    }
}

// ---------------------------------------------------------------------------
// Helpers
// ---------------------------------------------------------------------------
__global__ __launch_bounds__(256) void w_reorder(const float* __restrict__ w,
                                                 __half* __restrict__ wh,
                                                 int CO, int CIc) {
    int idx = blockIdx.x * 256 + threadIdx.x;
    int total = CO * CIc * 9;
    if (idx >= total) return;
    int K  = CIc * 9;
    int co = idx / K;
    int rem = idx - co * K;
    int r  = rem / CIc;
    int ci = rem - r * CIc;
    wh[idx] = __float2half_rn(w[(size_t)co * K + ci * 9 + r]);
}

__global__ __launch_bounds__(256) void x_tr(const float* __restrict__ x,
                                            __half* __restrict__ xt) {
    __shared__ uint16_t tile[64][65];
    const int b = blockIdx.z, p0 = blockIdx.x * 32, c0 = blockIdx.y * 64;
    const float* s = x + (size_t)b * 256 * 4096;
    const int t = threadIdx.x;
#pragma unroll
    for (int i = 0; i < 8; ++i) {
        int task = t + i * 256;
        int c = task >> 5, p = task & 31;
        tile[c][p] = __half_as_ushort(__float2half_rn(s[(size_t)(c0 + c) * 4096 + p0 + p]));
    }
    __syncthreads();
#pragma unroll
    for (int i = 0; i < 4; ++i) {
        int task = t + i * 256;
        int p = task >> 5, c2 = task & 31;
        uint32_t v = (uint32_t)tile[2 * c2][p] | ((uint32_t)tile[2 * c2 + 1][p] << 16);
        *reinterpret_cast<uint32_t*>(xt + (size_t)(b * 4096 + p0 + p) * 256 + c0 + 2 * c2) = v;
    }
}

// softmax over 256, summing 4 K-slice partials. blockIdx.x = b*256 + c.
__global__ __launch_bounds__(256) void softmax_h(const float* __restrict__ sp,
                                                 __half* __restrict__ a) {
    __shared__ float redmax[8];
    __shared__ float redsum[8];
    const int brow = blockIdx.x;
    const int b = brow >> 8, c = brow & 255;
    const int t = threadIdx.x;
    const size_t rbase = ((size_t)(b * 4) * 256 + c) * 256 + t;

    float v = sp[rbase] + sp[rbase + 65536] + sp[rbase + 131072] + sp[rbase + 196608];

    float m = v;
#pragma unroll
    for (int o = 16; o; o >>= 1) m = fmaxf(m, __shfl_xor_sync(0xffffffffu, m, o));
    if ((t & 31) == 0) redmax[t >> 5] = m;
    __syncthreads();
    m = redmax[0];
#pragma unroll
    for (int i = 1; i < 8; ++i) m = fmaxf(m, redmax[i]);

    float e = expf(v - m);
    float sum = e;
#pragma unroll
    for (int o = 16; o; o >>= 1) sum += __shfl_xor_sync(0xffffffffu, sum, o);
    if ((t & 31) == 0) redsum[t >> 5] = sum;
    __syncthreads();
    sum = 0.f;
#pragma unroll
    for (int i = 0; i < 8; ++i) sum += redsum[i];

    a[(size_t)brow * 256 + t] = __float2half_rn(e / sum);
}

// ---------------------------------------------------------------------------
extern "C" void kernel_launch(void* const* d_in, const int* in_sizes, int n_in,
                              void* d_out, int out_size)
{
    const float* x  = (const float*)d_in[0];
    const float* w1 = (const float*)d_in[1];
    const float* g1 = (const float*)d_in[2];
    const float* b1 = (const float*)d_in[3];
    const float* m1 = (const float*)d_in[4];
    const float* v1 = (const float*)d_in[5];
    const float* w2 = (const float*)d_in[6];
    const float* g2 = (const float*)d_in[7];
    const float* b2 = (const float*)d_in[8];
    const float* m2 = (const float*)d_in[9];
    const float* v2 = (const float*)d_in[10];
    float* out = (float*)d_out;

    __half *w1h, *w2h, *xt, *y1t, *y2, *y2t, *at;
    float* scp;
    cudaGetSymbolAddress((void**)&w1h, g_w1h);
    cudaGetSymbolAddress((void**)&w2h, g_w2h);
    cudaGetSymbolAddress((void**)&xt,  g_xt);
    cudaGetSymbolAddress((void**)&y1t, g_y1t);
    cudaGetSymbolAddress((void**)&y2,  g_y2);
    cudaGetSymbolAddress((void**)&y2t, g_y2t);
    cudaGetSymbolAddress((void**)&scp, g_scp);
    cudaGetSymbolAddress((void**)&at,  g_at);

    const int SMB64  = 49152;   // 2 stages x 24KB (conv, 4 CTAs/SM)
    const int SMB128 = 98304;   // 2 stages x 48KB (attention, 2 CTAs/SM)
    cudaFuncSetAttribute(gemm_fp16<0, 256, 64, 4>, cudaFuncAttributeMaxDynamicSharedMemorySize, SMB64);
    cudaFuncSetAttribute(gemm_fp16<0, 128, 64, 4>, cudaFuncAttributeMaxDynamicSharedMemorySize, SMB64);
    cudaFuncSetAttribute(gemm_fp16<1, 0, 128, 2>,  cudaFuncAttributeMaxDynamicSharedMemorySize, SMB128);
    cudaFuncSetAttribute(gemm_fp16<2, 0, 128, 2>,  cudaFuncAttributeMaxDynamicSharedMemorySize, SMB128);

    // ---- operand prep ----
    w_reorder<<<(128 * 2304 + 255) / 256, 256>>>(w1, w1h, 128, 256);
    w_reorder<<<(256 * 1152 + 255) / 256, 256>>>(w2, w2h, 256, 128);
    x_tr<<<dim3(128, 4, 16), 256>>>(x, xt);

    // conv1: writes y1^T directly. K=2304 -> 36 chunks, 4 CTAs/SM
    gemm_fp16<0, 256, 64, 4><<<dim3(64, 1, 16), 256, SMB64>>>(
        w1h, 2304, xt, 2304, g1, b1, m1, v1, nullptr, nullptr, y1t, nullptr);

    // conv2: writes y2 AND y2^T. K=1152 -> 18 chunks, 4 CTAs/SM
    gemm_fp16<0, 128, 64, 4><<<dim3(64, 2, 16), 256, SMB64>>>(
        w2h, 1152, y1t, 1152, g2, b2, m2, v2, nullptr, y2, y2t, nullptr);

    // scores partials: z = b*4+ks, each slice K=1024 -> 8 chunks
    gemm_fp16<1, 0, 128, 2><<<dim3(4, 2, 64), 256, SMB128>>>(
        y2, 4096, y2, 1024, nullptr, nullptr, nullptr, nullptr, nullptr,
        nullptr, nullptr, scp);
    softmax_h<<<4096, 256>>>(scp, at);

    // out = attn * q + x. K=256 -> 2 chunks
    gemm_fp16<2, 0, 128, 2><<<dim3(64, 2, 16), 256, SMB128>>>(
        at, 256, y2t, 256, nullptr, nullptr, nullptr, nullptr, x,
        nullptr, nullptr, out);
}

// round 16
// speedup vs baseline: 1.0247x; 1.0247x over previous
#include <cuda_runtime.h>
#include <cuda_fp16.h>
#include <math.h>
#include <stdint.h>

#define BN_EPS 1e-5f

// ---------------------------------------------------------------------------
// Global scratch
// ---------------------------------------------------------------------------
__device__ __half g_w1h[128*2304];                 // k = r*256+ci
__device__ __half g_w2h[256*1152];                 // k = r*128+ci
__device__ __half g_xt [16u*4096*256];             // x^T  [b][p][ci]
__device__ __half g_y1t[16u*4096*128];             // y1^T [b][p][ci]
__device__ __half g_y2 [16u*256*4096];             // y2   [b][c][p]
__device__ __half g_y2t[16u*4096*256];             // y2^T [b][p][c]
__device__ float  g_scp[64u*256*256];              // score partials [b*4+ks][c][d]
__device__ __half g_at [16u*256*256];              // attn

// ---------------------------------------------------------------------------
__device__ __forceinline__ uint32_t smem_u32(const void* p) {
    uint32_t a;
    asm("{ .reg .u64 t; cvta.to.shared.u64 t, %1; cvt.u32.u64 %0, t; }" : "=r"(a) : "l"(p));
    return a;
}
__device__ __forceinline__ void ldsm_x4(uint32_t addr, uint32_t r[4]) {
    asm volatile("ldmatrix.sync.aligned.m8n8.x4.shared.b16 {%0,%1,%2,%3}, [%4];"
                 : "=r"(r[0]), "=r"(r[1]), "=r"(r[2]), "=r"(r[3]) : "r"(addr));
}
__device__ __forceinline__ void mma16816(float d[4], const uint32_t a[4],
                                         uint32_t b0, uint32_t b1) {
    asm volatile(
        "mma.sync.aligned.m16n8k16.row.col.f32.f16.f16.f32 "
        "{%0,%1,%2,%3}, {%4,%5,%6,%7}, {%8,%9}, {%0,%1,%2,%3};"
        : "+f"(d[0]), "+f"(d[1]), "+f"(d[2]), "+f"(d[3])
        : "r"(a[0]), "r"(a[1]), "r"(a[2]), "r"(a[3]), "r"(b0), "r"(b1));
}
__device__ __forceinline__ uint32_t sw128(uint32_t off) {
    return off ^ ((off >> 3) & 0x70);
}
__device__ __forceinline__ void cp16(uint32_t dst, const void* src, int sz) {
    asm volatile("cp.async.cg.shared.global [%0], [%1], 16, %2;"
                 :: "r"(dst), "l"(src), "r"(sz) : "memory");
}
__device__ __forceinline__ void cp_commit() {
    asm volatile("cp.async.commit_group;" ::: "memory");
}

// ---------------------------------------------------------------------------
// fp16 GEMM on HMMA. CTA tile 128(M)x64(N), warps 4(M)x2(N), warp 32x32.
// Templated K-chunk (KCH = 64 or 128) and min-CTAs-per-SM (OCC).
// 2-stage cp.async, ONE sync per chunk.
// Stage = KCH*384 bytes: A = (KCH/64) blocks [128][64]h, B after A.
// MODE 0: conv (BN+SiLU). outh [c][p] (nullable), outt [p][c] transposed
//         (nullable). B = shifted transposed image planes, k = r*CI+ci.
// MODE 1: scores partial (x 1/16 -> fp32 partial; z = b*4+kslice)
// MODE 2: out (+ residual -> fp32)
// ---------------------------------------------------------------------------
template <int MODE, int CI, int KCH, int OCC>
__global__ __launch_bounds__(256, OCC)
void gemm_fp16(const __half* __restrict__ Ag, int lda,
               const __half* __restrict__ Bg, int K,
               const float* __restrict__ p0, const float* __restrict__ p1,
               const float* __restrict__ p2, const float* __restrict__ p3,
               const float* __restrict__ resid,
               __half* __restrict__ outh, __half* __restrict__ outt,
               float* __restrict__ outf)
{
    extern __shared__ char sm[];
    constexpr int STAGE  = KCH * 384;
    constexpr int ABYTES = KCH * 256;
    constexpr int GPR    = KCH / 8;
    constexpr int RSTEP  = 256 / GPR;
    const int t    = threadIdx.x;
    const int lane = t & 31, warp = t >> 5;
    const int wm   = (warp >> 1) * 32;
    const int wn   = (warp & 1) * 32;
    const int bm = blockIdx.y, bn = blockIdx.x;
    const int b  = (MODE == 1) ? (blockIdx.z >> 2) : blockIdx.z;
    const uint32_t sb = smem_u32(sm);

    const __half *Ab, *Bb;
    if (MODE == 0) {
        Ab = Ag; Bb = Bg + (size_t)b * 4096 * CI;
    } else if (MODE == 1) {
        const int ks = blockIdx.z & 3;
        size_t o = (size_t)b * 256 * 4096 + (size_t)ks * 1024;
        Ab = Ag + o; Bb = Bg + o;
    } else {
        Ab = Ag + (size_t)b * 256 * 256; Bb = Bg + (size_t)b * 4096 * 256;
    }
    const int ldb = (MODE == 1) ? 4096 : 256;

    float acc[2][4][4];
#pragma unroll
    for (int i = 0; i < 2; ++i)
#pragma unroll
        for (int j = 0; j < 4; ++j)
#pragma unroll
            for (int q = 0; q < 4; ++q) acc[i][j][q] = 0.f;

    // Prefetch task decomposition
    const int g   = t & (GPR - 1);
    const int m0  = t / GPR;
    const int blk = g >> 3;
    const int gin = g & 7;
    const uint32_t a_row0 = (uint32_t)((bm * 128 + m0) * lda + g * 8);
    uint32_t b_row0;
    if (MODE == 0) b_row0 = (uint32_t)((bn * 64 + m0) * CI + g * 8);
    else           b_row0 = (uint32_t)((bn * 64 + m0) * ldb + g * 8);

    // Hoisted ldsm addressing
    const int a_row = (lane & 7) + ((lane >> 3) & 1) * 8;
    const int a_chk = lane >> 4;
    const int b_row = (lane & 7) + ((lane >> 4) & 1) * 8;
    const int b_chk = (lane >> 3) & 1;
    uint32_t a_base[2], a_xor[2];
#pragma unroll
    for (int mt = 0; mt < 2; ++mt) {
        const int row = wm + mt * 16 + a_row;
        a_base[mt] = row * 128; a_xor[mt] = (row & 7) << 4;
    }
    uint32_t b_base[2], b_xor[2];
#pragma unroll
    for (int ng = 0; ng < 2; ++ng) {
        const int row = wn + ng * 16 + b_row;
        b_base[ng] = row * 128; b_xor[ng] = (row & 7) << 4;
    }

    auto prefetch = [&](int kt, int stage) {
        const uint32_t base = sb + stage * STAGE;
#pragma unroll
        for (int i = 0; i < 128 / RSTEP; ++i) {
            const int m = m0 + i * RSTEP;
            cp16(base + blk * 16384 + sw128(m * 128 + gin * 16),
                 Ab + a_row0 + (uint32_t)(i * RSTEP * lda) + kt * KCH, 16);
        }
        if (MODE == 0) {
            const int r   = (kt * KCH) / CI;
            const int ci0 = kt * KCH - r * CI;
            const int dh  = r / 3 - 1, dw = (r - (r / 3) * 3) - 1;
            const int delta = (dh * 64 + dw) * CI + ci0;
            const int hh = bn + dh;                    // tile = one image row
            const bool hok = (unsigned)hh < 64u;
#pragma unroll
            for (int i = 0; i < 64 / RSTEP; ++i) {
                const int m = m0 + i * RSTEP;
                const int ww = m + dw;
                const bool ok = hok && ((unsigned)ww < 64u);
                cp16(base + ABYTES + blk * 8192 + sw128(m * 128 + gin * 16),
                     Bb + (ok ? (b_row0 + (uint32_t)(i * RSTEP * CI) + delta) : 0u),
                     ok ? 16 : 0);
            }
        } else {
#pragma unroll
            for (int i = 0; i < 64 / RSTEP; ++i) {
                const int m = m0 + i * RSTEP;
                cp16(base + ABYTES + blk * 8192 + sw128(m * 128 + gin * 16),
                     Bb + b_row0 + (uint32_t)(i * RSTEP * ldb) + kt * KCH, 16);
            }
        }
    };

    const int nch = K / KCH;
    prefetch(0, 0);
    cp_commit();

    for (int kt = 0; kt < nch; ++kt) {
        const int stage = kt & 1;
        asm volatile("cp.async.wait_group 0;" ::: "memory");
        __syncthreads();
        if (kt + 1 < nch) {
            prefetch(kt + 1, stage ^ 1);
            cp_commit();
        }

        const uint32_t abase = sb + stage * STAGE;
        const uint32_t bbase = abase + ABYTES;
#pragma unroll
        for (int ks = 0; ks < KCH / 16; ++ks) {
            const uint32_t ablk = (uint32_t)(ks >> 2) * 16384;
            const uint32_t bblk = (uint32_t)(ks >> 2) * 8192;
            const uint32_t acol = (uint32_t)(((ks & 3) * 2 + a_chk) * 16);
            const uint32_t bcol = (uint32_t)(((ks & 3) * 2 + b_chk) * 16);
            uint32_t ah[2][4];
#pragma unroll
            for (int mt = 0; mt < 2; ++mt)
                ldsm_x4(abase + ablk + a_base[mt] + (acol ^ a_xor[mt]), ah[mt]);
#pragma unroll
            for (int ng = 0; ng < 2; ++ng) {
                uint32_t bh[4];
                ldsm_x4(bbase + bblk + b_base[ng] + (bcol ^ b_xor[ng]), bh);
#pragma unroll
                for (int mt = 0; mt < 2; ++mt) {
                    mma16816(acc[mt][2 * ng],     ah[mt], bh[0], bh[1]);
                    mma16816(acc[mt][2 * ng + 1], ah[mt], bh[2], bh[3]);
                }
            }
        }
    }

    // ----------------------- epilogue -----------------------
    const int r0 = bm * 128 + wm + (lane >> 2);
    const int c0 = bn * 64 + wn + (lane & 3) * 2;

    if (MODE == 0) {
        const int CO = gridDim.y * 128;
        __half2 vals[2][2][4];
#pragma unroll
        for (int mt = 0; mt < 2; ++mt) {
#pragma unroll
            for (int half = 0; half < 2; ++half) {
                const int co = r0 + mt * 16 + half * 8;
                const float scl = p0[co] * rsqrtf(p3[co] + BN_EPS);
                const float shf = p1[co] - p2[co] * scl;
#pragma unroll
                for (int nt = 0; nt < 4; ++nt) {
                    float y0 = acc[mt][nt][2 * half]     * scl + shf;
                    float y1 = acc[mt][nt][2 * half + 1] * scl + shf;
                    y0 = y0 / (1.f + expf(-y0));
                    y1 = y1 / (1.f + expf(-y1));
                    vals[mt][half][nt] = __floats2half2_rn(y0, y1);
                }
            }
        }
        if (outh) {
#pragma unroll
            for (int mt = 0; mt < 2; ++mt)
#pragma unroll
                for (int half = 0; half < 2; ++half) {
                    const int co = r0 + mt * 16 + half * 8;
                    __half* dst = outh + ((size_t)(b * CO + co)) * 4096;
#pragma unroll
                    for (int nt = 0; nt < 4; ++nt)
                        *reinterpret_cast<__half2*>(dst + c0 + nt * 8) = vals[mt][half][nt];
                }
        }
        if (outt) {
            uint16_t (*tt)[130] = reinterpret_cast<uint16_t(*)[130]>(sm);
            __syncthreads();
            const int co_lb = wm + (lane >> 2);
            const int p_lb  = wn + (lane & 3) * 2;
#pragma unroll
            for (int mt = 0; mt < 2; ++mt)
#pragma unroll
                for (int half = 0; half < 2; ++half) {
                    const int co_l = co_lb + mt * 16 + half * 8;
#pragma unroll
                    for (int nt = 0; nt < 4; ++nt) {
                        const int p_l = p_lb + nt * 8;
                        uint32_t v = *reinterpret_cast<uint32_t*>(&vals[mt][half][nt]);
                        tt[p_l][co_l]     = (uint16_t)v;
                        tt[p_l + 1][co_l] = (uint16_t)(v >> 16);
                    }
                }
            __syncthreads();
#pragma unroll
            for (int i = 0; i < 4; ++i) {
                const int idx = t + i * 256;
                const int row = idx >> 4, gg = idx & 15;
                uint32_t w0 = (uint32_t)tt[row][gg * 8 + 0] | ((uint32_t)tt[row][gg * 8 + 1] << 16);
                uint32_t w1 = (uint32_t)tt[row][gg * 8 + 2] | ((uint32_t)tt[row][gg * 8 + 3] << 16);
                uint32_t w2 = (uint32_t)tt[row][gg * 8 + 4] | ((uint32_t)tt[row][gg * 8 + 5] << 16);
                uint32_t w3 = (uint32_t)tt[row][gg * 8 + 6] | ((uint32_t)tt[row][gg * 8 + 7] << 16);
                __half* drow = outt + ((size_t)(b * 4096 + bn * 64 + row)) * CO + bm * 128 + gg * 8;
                *reinterpret_cast<uint4*>(drow) = make_uint4(w0, w1, w2, w3);
            }
        }
    } else if (MODE == 1) {
        float* obase = outf + (size_t)blockIdx.z * 256 * 256;
#pragma unroll
        for (int mt = 0; mt < 2; ++mt) {
#pragma unroll
            for (int half = 0; half < 2; ++half) {
                float* dst = obase + (size_t)(r0 + mt * 16 + half * 8) * 256;
#pragma unroll
                for (int nt = 0; nt < 4; ++nt) {
                    *reinterpret_cast<float2*>(dst + c0 + nt * 8) =
                        make_float2(acc[mt][nt][2 * half] * 0.0625f,
                                    acc[mt][nt][2 * half + 1] * 0.0625f);
                }
            }
        }
    } else {
#pragma unroll
        for (int mt = 0; mt < 2; ++mt) {
#pragma unroll
            for (int half = 0; half < 2; ++half) {
                const int c = r0 + mt * 16 + half * 8;
                const size_t base2 = ((size_t)(b * 256 + c)) * 4096;
#pragma unroll
                for (int nt = 0; nt < 4; ++nt) {
                    float2 rx = *reinterpret_cast<const float2*>(resid + base2 + c0 + nt * 8);
                    *reinterpret_cast<float2*>(outf + base2 + c0 + nt * 8) =
                        make_float2(acc[mt][nt][2 * half] + rx.x,
                                    acc[mt][nt][2 * half + 1] + rx.y);
                }
            }
        }
    }
}

// ---------------------------------------------------------------------------
// Helpers
// ---------------------------------------------------------------------------
__global__ __launch_bounds__(256) void w_reorder(const float* __restrict__ w,
                                                 __half* __restrict__ wh,
                                                 int CO, int CIc) {
    int idx = blockIdx.x * 256 + threadIdx.x;
    int total = CO * CIc * 9;
    if (idx >= total) return;
    int K  = CIc * 9;
    int co = idx / K;
    int rem = idx - co * K;
    int r  = rem / CIc;
    int ci = rem - r * CIc;
    wh[idx] = __float2half_rn(w[(size_t)co * K + ci * 9 + r]);
}

__global__ __launch_bounds__(256) void x_tr(const float* __restrict__ x,
                                            __half* __restrict__ xt) {
    __shared__ uint16_t tile[64][65];
    const int b = blockIdx.z, p0 = blockIdx.x * 32, c0 = blockIdx.y * 64;
    const float* s = x + (size_t)b * 256 * 4096;
    const int t = threadIdx.x;
#pragma unroll
    for (int i = 0; i < 8; ++i) {
        int task = t + i * 256;
        int c = task >> 5, p = task & 31;
        tile[c][p] = __half_as_ushort(__float2half_rn(s[(size_t)(c0 + c) * 4096 + p0 + p]));
    }
    __syncthreads();
#pragma unroll
    for (int i = 0; i < 4; ++i) {
        int task = t + i * 256;
        int p = task >> 5, c2 = task & 31;
        uint32_t v = (uint32_t)tile[2 * c2][p] | ((uint32_t)tile[2 * c2 + 1][p] << 16);
        *reinterpret_cast<uint32_t*>(xt + (size_t)(b * 4096 + p0 + p) * 256 + c0 + 2 * c2) = v;
    }
}

// softmax over 256, summing 4 K-slice partials. blockIdx.x = b*256 + c.
__global__ __launch_bounds__(256) void softmax_h(const float* __restrict__ sp,
                                                 __half* __restrict__ a) {
    __shared__ float redmax[8];
    __shared__ float redsum[8];
    const int brow = blockIdx.x;
    const int b = brow >> 8, c = brow & 255;
    const int t = threadIdx.x;
    const size_t rbase = ((size_t)(b * 4) * 256 + c) * 256 + t;

    float v = sp[rbase] + sp[rbase + 65536] + sp[rbase + 131072] + sp[rbase + 196608];

    float m = v;
#pragma unroll
    for (int o = 16; o; o >>= 1) m = fmaxf(m, __shfl_xor_sync(0xffffffffu, m, o));
    if ((t & 31) == 0) redmax[t >> 5] = m;
    __syncthreads();
    m = redmax[0];
#pragma unroll
    for (int i = 1; i < 8; ++i) m = fmaxf(m, redmax[i]);

    float e = expf(v - m);
    float sum = e;
#pragma unroll
    for (int o = 16; o; o >>= 1) sum += __shfl_xor_sync(0xffffffffu, sum, o);
    if ((t & 31) == 0) redsum[t >> 5] = sum;
    __syncthreads();
    sum = 0.f;
#pragma unroll
    for (int i = 0; i < 8; ++i) sum += redsum[i];

    a[(size_t)brow * 256 + t] = __float2half_rn(e / sum);
}

// ---------------------------------------------------------------------------
extern "C" void kernel_launch(void* const* d_in, const int* in_sizes, int n_in,
                              void* d_out, int out_size)
{
    const float* x  = (const float*)d_in[0];
    const float* w1 = (const float*)d_in[1];
    const float* g1 = (const float*)d_in[2];
    const float* b1 = (const float*)d_in[3];
    const float* m1 = (const float*)d_in[4];
    const float* v1 = (const float*)d_in[5];
    const float* w2 = (const float*)d_in[6];
    const float* g2 = (const float*)d_in[7];
    const float* b2 = (const float*)d_in[8];
    const float* m2 = (const float*)d_in[9];
    const float* v2 = (const float*)d_in[10];
    float* out = (float*)d_out;

    __half *w1h, *w2h, *xt, *y1t, *y2, *y2t, *at;
    float* scp;
    cudaGetSymbolAddress((void**)&w1h, g_w1h);
    cudaGetSymbolAddress((void**)&w2h, g_w2h);
    cudaGetSymbolAddress((void**)&xt,  g_xt);
    cudaGetSymbolAddress((void**)&y1t, g_y1t);
    cudaGetSymbolAddress((void**)&y2,  g_y2);
    cudaGetSymbolAddress((void**)&y2t, g_y2t);
    cudaGetSymbolAddress((void**)&scp, g_scp);
    cudaGetSymbolAddress((void**)&at,  g_at);

    const int SMB64  = 49152;   // 2 stages x 24KB (conv + out, 3 CTAs/SM)
    const int SMB128 = 98304;   // 2 stages x 48KB (scores, 2 CTAs/SM)
    cudaFuncSetAttribute(gemm_fp16<0, 256, 64, 3>, cudaFuncAttributeMaxDynamicSharedMemorySize, SMB64);
    cudaFuncSetAttribute(gemm_fp16<0, 128, 64, 3>, cudaFuncAttributeMaxDynamicSharedMemorySize, SMB64);
    cudaFuncSetAttribute(gemm_fp16<1, 0, 128, 2>,  cudaFuncAttributeMaxDynamicSharedMemorySize, SMB128);
    cudaFuncSetAttribute(gemm_fp16<2, 0, 64, 3>,   cudaFuncAttributeMaxDynamicSharedMemorySize, SMB64);

    // ---- operand prep ----
    w_reorder<<<(128 * 2304 + 255) / 256, 256>>>(w1, w1h, 128, 256);
    w_reorder<<<(256 * 1152 + 255) / 256, 256>>>(w2, w2h, 256, 128);
    x_tr<<<dim3(128, 4, 16), 256>>>(x, xt);

    // conv1: writes y1^T directly. K=2304 -> 36 chunks, 3 CTAs/SM
    gemm_fp16<0, 256, 64, 3><<<dim3(64, 1, 16), 256, SMB64>>>(
        w1h, 2304, xt, 2304, g1, b1, m1, v1, nullptr, nullptr, y1t, nullptr);

    // conv2: writes y2 AND y2^T. K=1152 -> 18 chunks, 3 CTAs/SM
    gemm_fp16<0, 128, 64, 3><<<dim3(64, 2, 16), 256, SMB64>>>(
        w2h, 1152, y1t, 1152, g2, b2, m2, v2, nullptr, y2, y2t, nullptr);

    // scores partials: z = b*4+ks, each slice K=1024 -> 8 chunks
    gemm_fp16<1, 0, 128, 2><<<dim3(4, 2, 64), 256, SMB128>>>(
        y2, 4096, y2, 1024, nullptr, nullptr, nullptr, nullptr, nullptr,
        nullptr, nullptr, scp);
    softmax_h<<<4096, 256>>>(scp, at);

    // out = attn * q + x. K=256 -> 4 chunks of 64, 3 CTAs/SM
    gemm_fp16<2, 0, 64, 3><<<dim3(64, 2, 16), 256, SMB64>>>(
        at, 256, y2t, 256, nullptr, nullptr, nullptr, nullptr, x,
        nullptr, nullptr, out);
}

// round 17
// speedup vs baseline: 1.0316x; 1.0068x over previous
#include <cuda_runtime.h>
#include <cuda_fp16.h>
#include <math.h>
#include <stdint.h>

#define BN_EPS 1e-5f

// ---------------------------------------------------------------------------
// Global scratch
// ---------------------------------------------------------------------------
__device__ __half g_w1h[128*2304];                 // k = r*256+ci
__device__ __half g_w2h[256*1152];                 // k = r*128+ci
__device__ __half g_xt [16u*4096*256];             // x^T  [b][p][ci]
__device__ __half g_y1t[16u*4096*128];             // y1^T [b][p][ci]
__device__ __half g_y2 [16u*256*4096];             // y2   [b][c][p]
__device__ __half g_y2t[16u*4096*256];             // y2^T [b][p][c]
__device__ float  g_scp[64u*256*256];              // score partials [b*4+ks][c][d]
__device__ __half g_at [16u*256*256];              // attn

// ---------------------------------------------------------------------------
__device__ __forceinline__ uint32_t smem_u32(const void* p) {
    uint32_t a;
    asm("{ .reg .u64 t; cvta.to.shared.u64 t, %1; cvt.u32.u64 %0, t; }" : "=r"(a) : "l"(p));
    return a;
}
__device__ __forceinline__ void ldsm_x4(uint32_t addr, uint32_t r[4]) {
    asm volatile("ldmatrix.sync.aligned.m8n8.x4.shared.b16 {%0,%1,%2,%3}, [%4];"
                 : "=r"(r[0]), "=r"(r[1]), "=r"(r[2]), "=r"(r[3]) : "r"(addr));
}
__device__ __forceinline__ void mma16816(float d[4], const uint32_t a[4],
                                         uint32_t b0, uint32_t b1) {
    asm volatile(
        "mma.sync.aligned.m16n8k16.row.col.f32.f16.f16.f32 "
        "{%0,%1,%2,%3}, {%4,%5,%6,%7}, {%8,%9}, {%0,%1,%2,%3};"
        : "+f"(d[0]), "+f"(d[1]), "+f"(d[2]), "+f"(d[3])
        : "r"(a[0]), "r"(a[1]), "r"(a[2]), "r"(a[3]), "r"(b0), "r"(b1));
}
__device__ __forceinline__ uint32_t sw128(uint32_t off) {
    return off ^ ((off >> 3) & 0x70);
}
__device__ __forceinline__ void cp16(uint32_t dst, const void* src, int sz) {
    asm volatile("cp.async.cg.shared.global [%0], [%1], 16, %2;"
                 :: "r"(dst), "l"(src), "r"(sz) : "memory");
}
__device__ __forceinline__ void cp_commit() {
    asm volatile("cp.async.commit_group;" ::: "memory");
}

// ---------------------------------------------------------------------------
// fp16 GEMM on HMMA. CTA tile 128(M)x64(N), warps 4(M)x2(N), warp 32x32.
// Templated K-chunk (KCH = 64 or 128) and min-CTAs-per-SM (OCC).
// 2-stage cp.async, ONE sync per chunk.
// Stage = KCH*384 bytes: A = (KCH/64) blocks [128][64]h, B after A.
// MODE 0: conv (BN+SiLU). outh [c][p] (nullable), outt [p][c] transposed
//         (nullable). B = shifted transposed image planes, k = r*CI+ci.
// MODE 1: scores partial (x 1/16 -> fp32 partial; z = b*4+kslice)
// MODE 2: out (+ residual -> fp32)
// ---------------------------------------------------------------------------
template <int MODE, int CI, int KCH, int OCC>
__global__ __launch_bounds__(256, OCC)
void gemm_fp16(const __half* __restrict__ Ag, int lda,
               const __half* __restrict__ Bg, int K,
               const float* __restrict__ p0, const float* __restrict__ p1,
               const float* __restrict__ p2, const float* __restrict__ p3,
               const float* __restrict__ resid,
               __half* __restrict__ outh, __half* __restrict__ outt,
               float* __restrict__ outf)
{
    extern __shared__ char sm[];
    constexpr int STAGE  = KCH * 384;
    constexpr int ABYTES = KCH * 256;
    constexpr int GPR    = KCH / 8;
    constexpr int RSTEP  = 256 / GPR;
    const int t    = threadIdx.x;
    const int lane = t & 31, warp = t >> 5;
    const int wm   = (warp >> 1) * 32;
    const int wn   = (warp & 1) * 32;
    const int bm = blockIdx.y, bn = blockIdx.x;
    const int b  = (MODE == 1) ? (blockIdx.z >> 2) : blockIdx.z;
    const uint32_t sb = smem_u32(sm);

    const __half *Ab, *Bb;
    if (MODE == 0) {
        Ab = Ag; Bb = Bg + (size_t)b * 4096 * CI;
    } else if (MODE == 1) {
        const int ks = blockIdx.z & 3;
        size_t o = (size_t)b * 256 * 4096 + (size_t)ks * 1024;
        Ab = Ag + o; Bb = Bg + o;
    } else {
        Ab = Ag + (size_t)b * 256 * 256; Bb = Bg + (size_t)b * 4096 * 256;
    }
    const int ldb = (MODE == 1) ? 4096 : 256;

    float acc[2][4][4];
#pragma unroll
    for (int i = 0; i < 2; ++i)
#pragma unroll
        for (int j = 0; j < 4; ++j)
#pragma unroll
            for (int q = 0; q < 4; ++q) acc[i][j][q] = 0.f;

    // Prefetch task decomposition
    const int g   = t & (GPR - 1);
    const int m0  = t / GPR;
    const int blk = g >> 3;
    const int gin = g & 7;
    const uint32_t a_row0 = (uint32_t)((bm * 128 + m0) * lda + g * 8);
    uint32_t b_row0;
    if (MODE == 0) b_row0 = (uint32_t)((bn * 64 + m0) * CI + g * 8);
    else           b_row0 = (uint32_t)((bn * 64 + m0) * ldb + g * 8);

    // Hoisted ldsm addressing
    const int a_row = (lane & 7) + ((lane >> 3) & 1) * 8;
    const int a_chk = lane >> 4;
    const int b_row = (lane & 7) + ((lane >> 4) & 1) * 8;
    const int b_chk = (lane >> 3) & 1;
    uint32_t a_base[2], a_xor[2];
#pragma unroll
    for (int mt = 0; mt < 2; ++mt) {
        const int row = wm + mt * 16 + a_row;
        a_base[mt] = row * 128; a_xor[mt] = (row & 7) << 4;
    }
    uint32_t b_base[2], b_xor[2];
#pragma unroll
    for (int ng = 0; ng < 2; ++ng) {
        const int row = wn + ng * 16 + b_row;
        b_base[ng] = row * 128; b_xor[ng] = (row & 7) << 4;
    }

    auto prefetch = [&](int kt, int stage) {
        const uint32_t base = sb + stage * STAGE;
#pragma unroll
        for (int i = 0; i < 128 / RSTEP; ++i) {
            const int m = m0 + i * RSTEP;
            cp16(base + blk * 16384 + sw128(m * 128 + gin * 16),
                 Ab + a_row0 + (uint32_t)(i * RSTEP * lda) + kt * KCH, 16);
        }
        if (MODE == 0) {
            const int r   = (kt * KCH) / CI;
            const int ci0 = kt * KCH - r * CI;
            const int dh  = r / 3 - 1, dw = (r - (r / 3) * 3) - 1;
            const int delta = (dh * 64 + dw) * CI + ci0;
            const int hh = bn + dh;                    // tile = one image row
            const bool hok = (unsigned)hh < 64u;
#pragma unroll
            for (int i = 0; i < 64 / RSTEP; ++i) {
                const int m = m0 + i * RSTEP;
                const int ww = m + dw;
                const bool ok = hok && ((unsigned)ww < 64u);
                cp16(base + ABYTES + blk * 8192 + sw128(m * 128 + gin * 16),
                     Bb + (ok ? (b_row0 + (uint32_t)(i * RSTEP * CI) + delta) : 0u),
                     ok ? 16 : 0);
            }
        } else {
#pragma unroll
            for (int i = 0; i < 64 / RSTEP; ++i) {
                const int m = m0 + i * RSTEP;
                cp16(base + ABYTES + blk * 8192 + sw128(m * 128 + gin * 16),
                     Bb + b_row0 + (uint32_t)(i * RSTEP * ldb) + kt * KCH, 16);
            }
        }
    };

    const int nch = K / KCH;
    prefetch(0, 0);
    cp_commit();

    for (int kt = 0; kt < nch; ++kt) {
        const int stage = kt & 1;
        asm volatile("cp.async.wait_group 0;" ::: "memory");
        __syncthreads();
        if (kt + 1 < nch) {
            prefetch(kt + 1, stage ^ 1);
            cp_commit();
        }

        const uint32_t abase = sb + stage * STAGE;
        const uint32_t bbase = abase + ABYTES;
#pragma unroll
        for (int ks = 0; ks < KCH / 16; ++ks) {
            const uint32_t ablk = (uint32_t)(ks >> 2) * 16384;
            const uint32_t bblk = (uint32_t)(ks >> 2) * 8192;
            const uint32_t acol = (uint32_t)(((ks & 3) * 2 + a_chk) * 16);
            const uint32_t bcol = (uint32_t)(((ks & 3) * 2 + b_chk) * 16);
            uint32_t ah[2][4];
#pragma unroll
            for (int mt = 0; mt < 2; ++mt)
                ldsm_x4(abase + ablk + a_base[mt] + (acol ^ a_xor[mt]), ah[mt]);
#pragma unroll
            for (int ng = 0; ng < 2; ++ng) {
                uint32_t bh[4];
                ldsm_x4(bbase + bblk + b_base[ng] + (bcol ^ b_xor[ng]), bh);
#pragma unroll
                for (int mt = 0; mt < 2; ++mt) {
                    mma16816(acc[mt][2 * ng],     ah[mt], bh[0], bh[1]);
                    mma16816(acc[mt][2 * ng + 1], ah[mt], bh[2], bh[3]);
                }
            }
        }
    }

    // ----------------------- epilogue -----------------------
    const int r0 = bm * 128 + wm + (lane >> 2);
    const int c0 = bn * 64 + wn + (lane & 3) * 2;

    if (MODE == 0) {
        const int CO = gridDim.y * 128;
        __half2 vals[2][2][4];
#pragma unroll
        for (int mt = 0; mt < 2; ++mt) {
#pragma unroll
            for (int half = 0; half < 2; ++half) {
                const int co = r0 + mt * 16 + half * 8;
                const float scl = p0[co] * rsqrtf(p3[co] + BN_EPS);
                const float shf = p1[co] - p2[co] * scl;
#pragma unroll
                for (int nt = 0; nt < 4; ++nt) {
                    float y0 = acc[mt][nt][2 * half]     * scl + shf;
                    float y1 = acc[mt][nt][2 * half + 1] * scl + shf;
                    y0 = y0 / (1.f + expf(-y0));
                    y1 = y1 / (1.f + expf(-y1));
                    vals[mt][half][nt] = __floats2half2_rn(y0, y1);
                }
            }
        }
        if (outh) {
#pragma unroll
            for (int mt = 0; mt < 2; ++mt)
#pragma unroll
                for (int half = 0; half < 2; ++half) {
                    const int co = r0 + mt * 16 + half * 8;
                    __half* dst = outh + ((size_t)(b * CO + co)) * 4096;
#pragma unroll
                    for (int nt = 0; nt < 4; ++nt)
                        *reinterpret_cast<__half2*>(dst + c0 + nt * 8) = vals[mt][half][nt];
                }
        }
        if (outt) {
            uint16_t (*tt)[130] = reinterpret_cast<uint16_t(*)[130]>(sm);
            __syncthreads();
            const int co_lb = wm + (lane >> 2);
            const int p_lb  = wn + (lane & 3) * 2;
#pragma unroll
            for (int mt = 0; mt < 2; ++mt)
#pragma unroll
                for (int half = 0; half < 2; ++half) {
                    const int co_l = co_lb + mt * 16 + half * 8;
#pragma unroll
                    for (int nt = 0; nt < 4; ++nt) {
                        const int p_l = p_lb + nt * 8;
                        uint32_t v = *reinterpret_cast<uint32_t*>(&vals[mt][half][nt]);
                        tt[p_l][co_l]     = (uint16_t)v;
                        tt[p_l + 1][co_l] = (uint16_t)(v >> 16);
                    }
                }
            __syncthreads();
#pragma unroll
            for (int i = 0; i < 4; ++i) {
                const int idx = t + i * 256;
                const int row = idx >> 4, gg = idx & 15;
                uint32_t w0 = (uint32_t)tt[row][gg * 8 + 0] | ((uint32_t)tt[row][gg * 8 + 1] << 16);
                uint32_t w1 = (uint32_t)tt[row][gg * 8 + 2] | ((uint32_t)tt[row][gg * 8 + 3] << 16);
                uint32_t w2 = (uint32_t)tt[row][gg * 8 + 4] | ((uint32_t)tt[row][gg * 8 + 5] << 16);
                uint32_t w3 = (uint32_t)tt[row][gg * 8 + 6] | ((uint32_t)tt[row][gg * 8 + 7] << 16);
                __half* drow = outt + ((size_t)(b * 4096 + bn * 64 + row)) * CO + bm * 128 + gg * 8;
                *reinterpret_cast<uint4*>(drow) = make_uint4(w0, w1, w2, w3);
            }
        }
    } else if (MODE == 1) {
        float* obase = outf + (size_t)blockIdx.z * 256 * 256;
#pragma unroll
        for (int mt = 0; mt < 2; ++mt) {
#pragma unroll
            for (int half = 0; half < 2; ++half) {
                float* dst = obase + (size_t)(r0 + mt * 16 + half * 8) * 256;
#pragma unroll
                for (int nt = 0; nt < 4; ++nt) {
                    *reinterpret_cast<float2*>(dst + c0 + nt * 8) =
                        make_float2(acc[mt][nt][2 * half] * 0.0625f,
                                    acc[mt][nt][2 * half + 1] * 0.0625f);
                }
            }
        }
    } else {
#pragma unroll
        for (int mt = 0; mt < 2; ++mt) {
#pragma unroll
            for (int half = 0; half < 2; ++half) {
                const int c = r0 + mt * 16 + half * 8;
                const size_t base2 = ((size_t)(b * 256 + c)) * 4096;
#pragma unroll
                for (int nt = 0; nt < 4; ++nt) {
                    float2 rx = *reinterpret_cast<const float2*>(resid + base2 + c0 + nt * 8);
                    *reinterpret_cast<float2*>(outf + base2 + c0 + nt * 8) =
                        make_float2(acc[mt][nt][2 * half] + rx.x,
                                    acc[mt][nt][2 * half + 1] + rx.y);
                }
            }
        }
    }
}

// ---------------------------------------------------------------------------
// Helpers
// ---------------------------------------------------------------------------
// Both weight tensors in one launch: idx < n1 -> w1, else w2.
__global__ __launch_bounds__(256) void w_reorder2(const float* __restrict__ w1,
                                                  const float* __restrict__ w2,
                                                  __half* __restrict__ w1h,
                                                  __half* __restrict__ w2h) {
    const int n1 = 128 * 2304;
    const int n2 = 256 * 1152;
    int idx = blockIdx.x * 256 + threadIdx.x;
    if (idx < n1) {
        int co = idx / 2304;
        int rem = idx - co * 2304;
        int r  = rem / 256;
        int ci = rem - r * 256;
        w1h[idx] = __float2half_rn(w1[(size_t)co * 2304 + ci * 9 + r]);
    } else if (idx < n1 + n2) {
        int j  = idx - n1;
        int co = j / 1152;
        int rem = j - co * 1152;
        int r  = rem / 128;
        int ci = rem - r * 128;
        w2h[j] = __float2half_rn(w2[(size_t)co * 1152 + ci * 9 + r]);
    }
}

__global__ __launch_bounds__(256) void x_tr(const float* __restrict__ x,
                                            __half* __restrict__ xt) {
    __shared__ uint16_t tile[64][65];
    const int b = blockIdx.z, p0 = blockIdx.x * 32, c0 = blockIdx.y * 64;
    const float* s = x + (size_t)b * 256 * 4096;
    const int t = threadIdx.x;
#pragma unroll
    for (int i = 0; i < 8; ++i) {
        int task = t + i * 256;
        int c = task >> 5, p = task & 31;
        tile[c][p] = __half_as_ushort(__float2half_rn(s[(size_t)(c0 + c) * 4096 + p0 + p]));
    }
    __syncthreads();
#pragma unroll
    for (int i = 0; i < 4; ++i) {
        int task = t + i * 256;
        int p = task >> 5, c2 = task & 31;
        uint32_t v = (uint32_t)tile[2 * c2][p] | ((uint32_t)tile[2 * c2 + 1][p] << 16);
        *reinterpret_cast<uint32_t*>(xt + (size_t)(b * 4096 + p0 + p) * 256 + c0 + 2 * c2) = v;
    }
}

// softmax over 256, summing 4 K-slice partials. blockIdx.x = b*256 + c.
__global__ __launch_bounds__(256) void softmax_h(const float* __restrict__ sp,
                                                 __half* __restrict__ a) {
    __shared__ float redmax[8];
    __shared__ float redsum[8];
    const int brow = blockIdx.x;
    const int b = brow >> 8, c = brow & 255;
    const int t = threadIdx.x;
    const size_t rbase = ((size_t)(b * 4) * 256 + c) * 256 + t;

    float v = sp[rbase] + sp[rbase + 65536] + sp[rbase + 131072] + sp[rbase + 196608];

    float m = v;
#pragma unroll
    for (int o = 16; o; o >>= 1) m = fmaxf(m, __shfl_xor_sync(0xffffffffu, m, o));
    if ((t & 31) == 0) redmax[t >> 5] = m;
    __syncthreads();
    m = redmax[0];
#pragma unroll
    for (int i = 1; i < 8; ++i) m = fmaxf(m, redmax[i]);

    float e = expf(v - m);
    float sum = e;
#pragma unroll
    for (int o = 16; o; o >>= 1) sum += __shfl_xor_sync(0xffffffffu, sum, o);
    if ((t & 31) == 0) redsum[t >> 5] = sum;
    __syncthreads();
    sum = 0.f;
#pragma unroll
    for (int i = 0; i < 8; ++i) sum += redsum[i];

    a[(size_t)brow * 256 + t] = __float2half_rn(e / sum);
}

// ---------------------------------------------------------------------------
extern "C" void kernel_launch(void* const* d_in, const int* in_sizes, int n_in,
                              void* d_out, int out_size)
{
    const float* x  = (const float*)d_in[0];
    const float* w1 = (const float*)d_in[1];
    const float* g1 = (const float*)d_in[2];
    const float* b1 = (const float*)d_in[3];
    const float* m1 = (const float*)d_in[4];
    const float* v1 = (const float*)d_in[5];
    const float* w2 = (const float*)d_in[6];
    const float* g2 = (const float*)d_in[7];
    const float* b2 = (const float*)d_in[8];
    const float* m2 = (const float*)d_in[9];
    const float* v2 = (const float*)d_in[10];
    float* out = (float*)d_out;

    __half *w1h, *w2h, *xt, *y1t, *y2, *y2t, *at;
    float* scp;
    cudaGetSymbolAddress((void**)&w1h, g_w1h);
    cudaGetSymbolAddress((void**)&w2h, g_w2h);
    cudaGetSymbolAddress((void**)&xt,  g_xt);
    cudaGetSymbolAddress((void**)&y1t, g_y1t);
    cudaGetSymbolAddress((void**)&y2,  g_y2);
    cudaGetSymbolAddress((void**)&y2t, g_y2t);
    cudaGetSymbolAddress((void**)&scp, g_scp);
    cudaGetSymbolAddress((void**)&at,  g_at);

    const int SMB64 = 49152;   // 2 stages x 24KB (all GEMMs, 3 CTAs/SM)
    cudaFuncSetAttribute(gemm_fp16<0, 256, 64, 3>, cudaFuncAttributeMaxDynamicSharedMemorySize, SMB64);
    cudaFuncSetAttribute(gemm_fp16<0, 128, 64, 3>, cudaFuncAttributeMaxDynamicSharedMemorySize, SMB64);
    cudaFuncSetAttribute(gemm_fp16<1, 0, 64, 3>,   cudaFuncAttributeMaxDynamicSharedMemorySize, SMB64);
    cudaFuncSetAttribute(gemm_fp16<2, 0, 64, 3>,   cudaFuncAttributeMaxDynamicSharedMemorySize, SMB64);

    // ---- operand prep ----
    w_reorder2<<<(128 * 2304 + 256 * 1152 + 255) / 256, 256>>>(w1, w2, w1h, w2h);
    x_tr<<<dim3(128, 4, 16), 256>>>(x, xt);

    // conv1: writes y1^T directly. K=2304 -> 36 chunks, 3 CTAs/SM
    gemm_fp16<0, 256, 64, 3><<<dim3(64, 1, 16), 256, SMB64>>>(
        w1h, 2304, xt, 2304, g1, b1, m1, v1, nullptr, nullptr, y1t, nullptr);

    // conv2: writes y2 AND y2^T. K=1152 -> 18 chunks, 3 CTAs/SM
    gemm_fp16<0, 128, 64, 3><<<dim3(64, 2, 16), 256, SMB64>>>(
        w2h, 1152, y1t, 1152, g2, b2, m2, v2, nullptr, y2, y2t, nullptr);

    // scores partials: z = b*4+ks, each slice K=1024 -> 16 chunks of 64, 3 CTAs/SM
    gemm_fp16<1, 0, 64, 3><<<dim3(4, 2, 64), 256, SMB64>>>(
        y2, 4096, y2, 1024, nullptr, nullptr, nullptr, nullptr, nullptr,
        nullptr, nullptr, scp);
    softmax_h<<<4096, 256>>>(scp, at);

    // out = attn * q + x. K=256 -> 4 chunks of 64, 3 CTAs/SM
    gemm_fp16<2, 0, 64, 3><<<dim3(64, 2, 16), 256, SMB64>>>(
        at, 256, y2t, 256, nullptr, nullptr, nullptr, nullptr, x,
        nullptr, nullptr, out);
}